// round 1
// baseline (speedup 1.0000x reference)
#include <cuda_runtime.h>
#include <math.h>

#define TBL   524288u                 // T = 2^19 entries per level
#define MASK8 ((TBL - 1u) * 8u)       // byte-space mask: 0x3FFFF8
#define PR1   2654435761u
#define PR2   805459861u

struct Res16 { int r[16]; };

__device__ __forceinline__ float2 lerp2(float2 a, float2 b, float t) {
    return make_float2(fmaf(t, b.x - a.x, a.x), fmaf(t, b.y - a.y, a.y));
}

// One level of hash-grid trilinear interpolation for one point.
// base points at this level's [T,2] float table. All hash math done in
// byte-offset space (values pre-shifted by 3) so per-corner cost is
// 1 LOP3 (xor+mask) + 1 IMAD.WIDE (addr) + 1 LDG.64.
__device__ __forceinline__ float2 enc_level(
    const char* __restrict__ base, float px, float py, float pz, float r)
{
    float xs = px * r, ys = py * r, zs = pz * r;
    int ix = (int)xs, iy = (int)ys, iz = (int)zs;       // x in [0,1) -> trunc == floor
    float fx = xs - (float)ix;
    float fy = ys - (float)iy;
    float fz = zs - (float)iz;

    // byte-space partial hashes (low 19 hash bits live in bits [3:22])
    unsigned hx0 = ((unsigned)ix) << 3;
    unsigned hx1 = hx0 + 8u;
    unsigned hy0 = (unsigned)iy * (PR1 * 8u);
    unsigned hy1 = hy0 + (PR1 * 8u);
    unsigned hz0 = (unsigned)iz * (PR2 * 8u);
    unsigned hz1 = hz0 + (PR2 * 8u);
    unsigned a00 = hy0 ^ hz0;
    unsigned a01 = hy0 ^ hz1;
    unsigned a10 = hy1 ^ hz0;
    unsigned a11 = hy1 ^ hz1;

    // e_{x}{y}{z}: 8 corner gathers (float2 each). Issue all loads first -> MLP=8.
    float2 e000 = __ldg((const float2*)(base + ((hx0 ^ a00) & MASK8)));
    float2 e001 = __ldg((const float2*)(base + ((hx0 ^ a01) & MASK8)));
    float2 e010 = __ldg((const float2*)(base + ((hx0 ^ a10) & MASK8)));
    float2 e011 = __ldg((const float2*)(base + ((hx0 ^ a11) & MASK8)));
    float2 e100 = __ldg((const float2*)(base + ((hx1 ^ a00) & MASK8)));
    float2 e101 = __ldg((const float2*)(base + ((hx1 ^ a01) & MASK8)));
    float2 e110 = __ldg((const float2*)(base + ((hx1 ^ a10) & MASK8)));
    float2 e111 = __ldg((const float2*)(base + ((hx1 ^ a11) & MASK8)));

    // trilinear lerp tree, same structure as reference
    float2 c00 = lerp2(e000, e100, fx);
    float2 c01 = lerp2(e001, e101, fx);
    float2 c10 = lerp2(e010, e110, fx);
    float2 c11 = lerp2(e011, e111, fx);
    float2 c0  = lerp2(c00, c10, fy);
    float2 c1  = lerp2(c01, c11, fy);
    return lerp2(c0, c1, fz);
}

// 8 threads per point; each thread handles 2 consecutive levels and writes
// one float4 (2 levels x 2 feats). A warp covers 4 points = 512B of
// contiguous output -> coalesced STG.128.
__global__ void __launch_bounds__(256, 4) hashenc_kernel(
    const float* __restrict__ x,
    const float* __restrict__ emb,
    float* __restrict__ out,
    unsigned npts, Res16 rr)
{
    unsigned tid = blockIdx.x * 256u + threadIdx.x;
    unsigned pt = tid >> 3;
    if (pt >= npts) return;
    unsigned chunk = tid & 7u;
    unsigned lvl = chunk * 2u;

    float px = __ldg(x + 3u * pt + 0u);
    float py = __ldg(x + 3u * pt + 1u);
    float pz = __ldg(x + 3u * pt + 2u);

    const char* base0 = (const char*)emb + (size_t)lvl * (size_t)(TBL * 8u);
    float r0 = (float)rr.r[lvl];
    float r1 = (float)rr.r[lvl + 1u];

    float2 f0 = enc_level(base0, px, py, pz, r0);
    float2 f1 = enc_level(base0 + (size_t)(TBL * 8u), px, py, pz, r1);

    float4 o = make_float4(f0.x, f0.y, f1.x, f1.y);
    *(float4*)(out + (size_t)pt * 32u + chunk * 4u) = o;
}

extern "C" void kernel_launch(void* const* d_in, const int* in_sizes, int n_in,
                              void* d_out, int out_size)
{
    const float* x   = (const float*)d_in[0];   // [2097152, 3] f32
    const float* emb = (const float*)d_in[1];   // [16, 524288, 2] f32
    float* out = (float*)d_out;                 // [2097152, 32] f32

    unsigned npts = (unsigned)(in_sizes[0] / 3);

    // Resolutions via the exact reference formula in double precision
    // (same libm as the Python reference on this host; floor margins are
    // as small as 0.004 at level 14, so do NOT hardcode).
    Res16 rr;
    double b = exp((log(2048.0) - log(16.0)) / 15.0);
    for (int i = 0; i < 16; i++)
        rr.r[i] = (int)floor(16.0 * pow(b, (double)i));

    unsigned total = npts * 8u;
    unsigned blocks = (total + 255u) / 256u;
    hashenc_kernel<<<blocks, 256>>>(x, emb, out, npts, rr);
}

// round 2
// speedup vs baseline: 1.0516x; 1.0516x over previous
#include <cuda_runtime.h>
#include <math.h>

#define TBL    524288u                 // T = 2^19 entries per level
#define MASK8  ((TBL - 1u) * 8u)       // byte-space mask: 0x3FFFF8
#define MASK16 (MASK8 & ~8u)           // 16B-aligned byte mask: 0x3FFFF0
#define PR1    2654435761u
#define PR2    805459861u

struct Res16 { int r[16]; };

__device__ __forceinline__ float2 lerp2(float2 a, float2 b, float t) {
    return make_float2(fmaf(t, b.x - a.x, a.x), fmaf(t, b.y - a.y, a.y));
}

// One level of hash-grid trilinear interpolation for one point.
// Hash math in byte-offset space (entry index pre-shifted by 3).
//
// Key trick: hash is ix*1 ^ iy*P1 ^ iz*P2, so ix enters the low bits
// linearly. For EVEN ix, corners (ix,·,·) and (ix+1,·,·) live in adjacent
// table entries forming one aligned 16B block -> a single LDG.128 fetches
// both x-corners (1 sector instead of 2). ix parity is shared by all 4
// corner pairs of a level -> one divergent branch per level; the extra
// issue/branch cost lands on the idle issue pipe, the sector saving lands
// on the saturated L1tex pipe.
__device__ __forceinline__ float2 enc_level(
    const char* __restrict__ base, float px, float py, float pz, float r)
{
    float xs = px * r, ys = py * r, zs = pz * r;
    int ix = (int)xs, iy = (int)ys, iz = (int)zs;       // x in [0,1) -> trunc == floor
    float fx = xs - (float)ix;
    float fy = ys - (float)iy;
    float fz = zs - (float)iz;

    unsigned hx0 = ((unsigned)ix) << 3;
    unsigned hy0 = (unsigned)iy * (PR1 * 8u);
    unsigned hy1 = hy0 + (PR1 * 8u);
    unsigned hz0 = (unsigned)iz * (PR2 * 8u);
    unsigned hz1 = hz0 + (PR2 * 8u);
    unsigned a00 = hy0 ^ hz0;
    unsigned a01 = hy0 ^ hz1;
    unsigned a10 = hy1 ^ hz0;
    unsigned a11 = hy1 ^ hz1;

    float2 e000, e001, e010, e011, e100, e101, e110, e111;

    if ((hx0 & 8u) == 0u) {
        // ix even: 4 x LDG.128, each holding both x-corners of one (y,z) pair.
        // Within the 16B block, corner ix sits at half selected by bit3 of a.
        float4 v00 = __ldg((const float4*)(base + ((hx0 ^ a00) & MASK16)));
        float4 v01 = __ldg((const float4*)(base + ((hx0 ^ a01) & MASK16)));
        float4 v10 = __ldg((const float4*)(base + ((hx0 ^ a10) & MASK16)));
        float4 v11 = __ldg((const float4*)(base + ((hx0 ^ a11) & MASK16)));
        bool s00 = (a00 & 8u) != 0u;
        bool s01 = (a01 & 8u) != 0u;
        bool s10 = (a10 & 8u) != 0u;
        bool s11 = (a11 & 8u) != 0u;
        e000 = s00 ? make_float2(v00.z, v00.w) : make_float2(v00.x, v00.y);
        e100 = s00 ? make_float2(v00.x, v00.y) : make_float2(v00.z, v00.w);
        e001 = s01 ? make_float2(v01.z, v01.w) : make_float2(v01.x, v01.y);
        e101 = s01 ? make_float2(v01.x, v01.y) : make_float2(v01.z, v01.w);
        e010 = s10 ? make_float2(v10.z, v10.w) : make_float2(v10.x, v10.y);
        e110 = s10 ? make_float2(v10.x, v10.y) : make_float2(v10.z, v10.w);
        e011 = s11 ? make_float2(v11.z, v11.w) : make_float2(v11.x, v11.y);
        e111 = s11 ? make_float2(v11.x, v11.y) : make_float2(v11.z, v11.w);
    } else {
        // ix odd: (ix+1) carries -> unrelated entries; 8 x LDG.64.
        unsigned hx1 = hx0 + 8u;
        e000 = __ldg((const float2*)(base + ((hx0 ^ a00) & MASK8)));
        e001 = __ldg((const float2*)(base + ((hx0 ^ a01) & MASK8)));
        e010 = __ldg((const float2*)(base + ((hx0 ^ a10) & MASK8)));
        e011 = __ldg((const float2*)(base + ((hx0 ^ a11) & MASK8)));
        e100 = __ldg((const float2*)(base + ((hx1 ^ a00) & MASK8)));
        e101 = __ldg((const float2*)(base + ((hx1 ^ a01) & MASK8)));
        e110 = __ldg((const float2*)(base + ((hx1 ^ a10) & MASK8)));
        e111 = __ldg((const float2*)(base + ((hx1 ^ a11) & MASK8)));
    }

    // trilinear lerp tree, same structure as reference
    float2 c00 = lerp2(e000, e100, fx);
    float2 c01 = lerp2(e001, e101, fx);
    float2 c10 = lerp2(e010, e110, fx);
    float2 c11 = lerp2(e011, e111, fx);
    float2 c0  = lerp2(c00, c10, fy);
    float2 c1  = lerp2(c01, c11, fy);
    return lerp2(c0, c1, fz);
}

// 8 threads per point; each thread handles 2 consecutive levels and writes
// one float4 (2 levels x 2 feats). A warp covers 4 points = 512B of
// contiguous output -> coalesced STG.128.
__global__ void __launch_bounds__(256, 4) hashenc_kernel(
    const float* __restrict__ x,
    const float* __restrict__ emb,
    float* __restrict__ out,
    unsigned npts, Res16 rr)
{
    unsigned tid = blockIdx.x * 256u + threadIdx.x;
    unsigned pt = tid >> 3;
    if (pt >= npts) return;
    unsigned chunk = tid & 7u;
    unsigned lvl = chunk * 2u;

    float px = __ldg(x + 3u * pt + 0u);
    float py = __ldg(x + 3u * pt + 1u);
    float pz = __ldg(x + 3u * pt + 2u);

    const char* base0 = (const char*)emb + (size_t)lvl * (size_t)(TBL * 8u);
    float r0 = (float)rr.r[lvl];
    float r1 = (float)rr.r[lvl + 1u];

    float2 f0 = enc_level(base0, px, py, pz, r0);
    float2 f1 = enc_level(base0 + (size_t)(TBL * 8u), px, py, pz, r1);

    float4 o = make_float4(f0.x, f0.y, f1.x, f1.y);
    *(float4*)(out + (size_t)pt * 32u + chunk * 4u) = o;
}

extern "C" void kernel_launch(void* const* d_in, const int* in_sizes, int n_in,
                              void* d_out, int out_size)
{
    const float* x   = (const float*)d_in[0];   // [2097152, 3] f32
    const float* emb = (const float*)d_in[1];   // [16, 524288, 2] f32
    float* out = (float*)d_out;                 // [2097152, 32] f32

    unsigned npts = (unsigned)(in_sizes[0] / 3);

    // Resolutions via the exact reference formula in double precision
    // (floor margins as small as 0.004 at level 14 -> do NOT hardcode).
    Res16 rr;
    double b = exp((log(2048.0) - log(16.0)) / 15.0);
    for (int i = 0; i < 16; i++)
        rr.r[i] = (int)floor(16.0 * pow(b, (double)i));

    unsigned total = npts * 8u;
    unsigned blocks = (total + 255u) / 256u;
    hashenc_kernel<<<blocks, 256>>>(x, emb, out, npts, rr);
}